// round 12
// baseline (speedup 1.0000x reference)
#include <cuda_runtime.h>
#include <float.h>

#define NB     2
#define NN     8192
#define KNN    20
#define COUT   64
#define NCLASS 40
#define BN_EPS 1e-5f
#define EPT    8

// Scratch (no allocations allowed)
__device__ alignas(16) float    g_A[NB * NN];
__device__ alignas(16) float    g_B[NB * NN];
__device__ unsigned g_rmax[NB * COUT];   // per-(b,o) max(h) as monotone uint (h>=0)
__device__ float    g_rsum[NB * COUT];   // per-(b,o) sum(h)

// ---------------------------------------------------------------------------
// Compare-exchange helpers — ALL register indices compile-time constant.
// Global bitonic rule: at stage k, element i merges ascending iff (i&k)==0.
// ---------------------------------------------------------------------------
__device__ __forceinline__ void ce(float& a, float& b, bool up) {
    float mn = fminf(a, b), mx = fmaxf(a, b);
    a = up ? mn : mx;
    b = up ? mx : mn;
}

__device__ __forceinline__ void reg_merge(float v[EPT], bool d) {
    ce(v[0], v[4], d); ce(v[1], v[5], d); ce(v[2], v[6], d); ce(v[3], v[7], d);
    ce(v[0], v[2], d); ce(v[1], v[3], d); ce(v[4], v[6], d); ce(v[5], v[7], d);
    ce(v[0], v[1], d); ce(v[2], v[3], d); ce(v[4], v[5], d); ce(v[6], v[7], d);
}

__device__ __forceinline__ void sort8(float v[EPT], bool d8) {
    ce(v[0], v[1], true);  ce(v[2], v[3], false);
    ce(v[4], v[5], true);  ce(v[6], v[7], false);
    ce(v[0], v[2], true);  ce(v[1], v[3], true);
    ce(v[4], v[6], false); ce(v[5], v[7], false);
    ce(v[0], v[1], true);  ce(v[2], v[3], true);
    ce(v[4], v[5], false); ce(v[6], v[7], false);
    reg_merge(v, d8);
}

__device__ __forceinline__ void warp_merge(float v[EPT], bool d, int xm_start, int u) {
    for (int xm = xm_start; xm >= 1; xm >>= 1) {
        bool lowup = (((u & xm) == 0) == d);
        #pragma unroll
        for (int m = 0; m < EPT; m++) {
            float pv = __shfl_xor_sync(0xffffffffu, v[m], xm);
            v[m] = lowup ? fminf(v[m], pv) : fmaxf(v[m], pv);
        }
    }
    reg_merge(v, d);
}

// Subgroup-local merge over a 1024-element chunk held by 128 threads.
// __syncthreads is block-wide — all subgroups execute identical stage counts.
__device__ __forceinline__ void sub_merge(float v[EPT], float4* sA, int u,
                                          bool d, int jstart) {
    float4* sB = sA + 128;
    for (int j = jstart; j >= 256; j >>= 1) {
        sA[u] = make_float4(v[0], v[1], v[2], v[3]);
        sB[u] = make_float4(v[4], v[5], v[6], v[7]);
        __syncthreads();
        const int  pt    = u ^ (j >> 3);
        const bool lowup = (((u & (j >> 3)) == 0) == d);
        float4 pa = sA[pt], pb = sB[pt];
        v[0] = lowup ? fminf(v[0], pa.x) : fmaxf(v[0], pa.x);
        v[1] = lowup ? fminf(v[1], pa.y) : fmaxf(v[1], pa.y);
        v[2] = lowup ? fminf(v[2], pa.z) : fmaxf(v[2], pa.z);
        v[3] = lowup ? fminf(v[3], pa.w) : fmaxf(v[3], pa.w);
        v[4] = lowup ? fminf(v[4], pb.x) : fmaxf(v[4], pb.x);
        v[5] = lowup ? fminf(v[5], pb.y) : fmaxf(v[5], pb.y);
        v[6] = lowup ? fminf(v[6], pb.z) : fmaxf(v[6], pb.z);
        v[7] = lowup ? fminf(v[7], pb.w) : fmaxf(v[7], pb.w);
        __syncthreads();
    }
    warp_merge(v, d, 16, u);
}

__device__ __forceinline__ float4 f4ce(float4 a, float4 b, bool mn) {
    float4 r;
    r.x = mn ? fminf(a.x, b.x) : fmaxf(a.x, b.x);
    r.y = mn ? fminf(a.y, b.y) : fmaxf(a.y, b.y);
    r.z = mn ? fminf(a.z, b.z) : fmaxf(a.z, b.z);
    r.w = mn ? fminf(a.w, b.w) : fmaxf(a.w, b.w);
    return r;
}

// ---------------------------------------------------------------------------
// K1: sort each 1024-chunk (k = 2..1024). grid (8, NB) x 128 threads.
// Also zeroes the global accumulators (deterministic per launch).
// ---------------------------------------------------------------------------
__global__ void __launch_bounds__(128, 1) k_sort1024(const float* __restrict__ x) {
    __shared__ float4 s[256];
    const int t = threadIdx.x;
    const int b = blockIdx.y, cx = blockIdx.x;
    if (b == 0 && cx == 0) { g_rmax[t] = 0u; g_rsum[t] = 0.f; }   // 128 == NB*COUT

    const float4* src = (const float4*)(x + b * NN + cx * 1024);
    float v[EPT];
    { float4 a = src[t * 2], c = src[t * 2 + 1];
      v[0]=a.x; v[1]=a.y; v[2]=a.z; v[3]=a.w;
      v[4]=c.x; v[5]=c.y; v[6]=c.z; v[7]=c.w; }

    sort8(v, (t & 1) == 0);                            // k = 2,4,8
    for (int k = 16; k <= 256; k <<= 1)                // k = 16..256
        warp_merge(v, (t & (k >> 3)) == 0, k >> 4, t);
    sub_merge(v, s, t, (t & 64) == 0, 256);            // k = 512
    sub_merge(v, s, t, (cx & 1) == 0, 512);            // k = 1024

    float4* dst = (float4*)(g_A + b * NN + cx * 1024);
    dst[t * 2]     = make_float4(v[0], v[1], v[2], v[3]);
    dst[t * 2 + 1] = make_float4(v[4], v[5], v[6], v[7]);
}

// ---------------------------------------------------------------------------
// Merge stage for k = 1024<<L (cross substages as load-time butterflies).
// grid (8, NB) x 128 threads. L=1: g_A -> g_B.  L=2: g_B -> g_A. (Proven R7.)
// ---------------------------------------------------------------------------
template<int L>
__global__ void __launch_bounds__(128, 1) k_merge() {
    __shared__ float4 s[256];
    const int t = threadIdx.x;
    const int b = blockIdx.y, cx = blockIdx.x;
    const float* __restrict__ srcp = (L == 2) ? g_B : g_A;
    float*       __restrict__ dstp = (L == 2) ? g_A : g_B;
    const float4* src = (const float4*)(srcp + b * NN);

    bool asc, km1, km2 = false;
    if (L == 1) {
        asc = ((cx >> 1) & 1) == 0;
        km1 = asc == ((cx & 1) == 0);
    } else {
        asc = ((cx >> 2) & 1) == 0;
        km1 = asc == (((cx >> 1) & 1) == 0);
        km2 = asc == ((cx & 1) == 0);
    }

    float v[EPT];
    #pragma unroll
    for (int g = 0; g < 2; g++) {
        const int o = t * 2 + g;
        float4 r;
        if (L == 1) {
            r = f4ce(src[cx * 256 + o], src[(cx ^ 1) * 256 + o], km1);
        } else {
            float4 a0 = src[cx * 256 + o],       a1 = src[(cx ^ 1) * 256 + o];
            float4 a2 = src[(cx ^ 2) * 256 + o], a3 = src[(cx ^ 3) * 256 + o];
            r = f4ce(f4ce(a0, a2, km1), f4ce(a1, a3, km1), km2);
        }
        v[g*4+0]=r.x; v[g*4+1]=r.y; v[g*4+2]=r.z; v[g*4+3]=r.w;
    }

    sub_merge(v, s, t, asc, 512);

    float4* dst = (float4*)(dstp + b * NN + cx * 1024);
    dst[t * 2]     = make_float4(v[0], v[1], v[2], v[3]);
    dst[t * 2 + 1] = make_float4(v[4], v[5], v[6], v[7]);
}

// ---------------------------------------------------------------------------
// K4: final k=8192 merge + K-window + per-chunk channel reduction, fused.
// grid (8, NB) x 384 thr. Subgroup g in {0,1,2} computes final sorted chunk
// cx+g-1 (clamped) -> 3-chunk span in smem; window for middle chunk runs with
// halo resident; then 12 warps x (2 channels/lane) reduce h over the 1024
// points and publish (max,sum) partials via atomics.
// ---------------------------------------------------------------------------
__global__ void __launch_bounds__(384, 1)
k_merge3win_red(const float* __restrict__ conv_w, const float* __restrict__ gamma,
                const float* __restrict__ beta,   const float* __restrict__ mean,
                const float* __restrict__ var) {
    __shared__ float smf[3 * 1024];
    __shared__ float sdn[1024], sdx[1024];
    __shared__ float pmx[12][COUT], psm[12][COUT];
    float4* sm4 = (float4*)smf;
    const int t = threadIdx.x;
    const int cx = blockIdx.x, b = blockIdx.y;
    const int g = t / 128, u = t & 127;
    int c = cx + g - 1;
    c = (c < 0) ? 0 : ((c > 7) ? 7 : c);

    const bool km1 = (c & 4) == 0;
    const bool km2 = (c & 2) == 0;
    const bool km3 = (c & 1) == 0;

    const float4* src = (const float4*)(g_A + b * NN);
    float v[EPT];
    #pragma unroll
    for (int h = 0; h < 2; h++) {
        const int o = u * 2 + h;
        float4 a0 = src[c * 256 + o],       a1 = src[(c ^ 1) * 256 + o];
        float4 a2 = src[(c ^ 2) * 256 + o], a3 = src[(c ^ 3) * 256 + o];
        float4 a4 = src[(c ^ 4) * 256 + o], a5 = src[(c ^ 5) * 256 + o];
        float4 a6 = src[(c ^ 6) * 256 + o], a7 = src[(c ^ 7) * 256 + o];
        float4 u0 = f4ce(a0, a4, km1), u2 = f4ce(a2, a6, km1);
        float4 u1 = f4ce(a1, a5, km1), u3 = f4ce(a3, a7, km1);
        float4 r  = f4ce(f4ce(u0, u2, km2), f4ce(u1, u3, km2), km3);
        v[h*4+0] = r.x; v[h*4+1] = r.y; v[h*4+2] = r.z; v[h*4+3] = r.w;
    }

    sub_merge(v, sm4 + g * 256, u, true, 512);   // final local merge (ascending)

    { float4* nat = sm4 + g * 256;               // natural layout
      nat[u * 2]     = make_float4(v[0], v[1], v[2], v[3]);
      nat[u * 2 + 1] = make_float4(v[4], v[5], v[6], v[7]); }
    __syncthreads();

    // ---- window for middle chunk: 3 interleaved expansions per thread ----
    const int off = 1024 - cx * 1024;            // smem idx of global pos p = p+off
    int   pl[3];
    pl[0] = t; pl[1] = t + 384;
    const bool v2 = (t + 768) < 1024;
    pl[2] = v2 ? (t + 768) : 1023;

    float xv[3], dl[3], dr[3];
    int lo[3], hi[3];
    #pragma unroll
    for (int e = 0; e < 3; e++) {
        int p = cx * 1024 + pl[e];
        lo[e] = p; hi[e] = p;
        xv[e] = smf[p + off];
        dl[e] = (p > 0)      ? (xv[e] - smf[p - 1 + off]) : FLT_MAX;
        dr[e] = (p < NN - 1) ? (smf[p + 1 + off] - xv[e]) : FLT_MAX;
    }
    for (int it = 1; it < KNN; it++) {
        #pragma unroll
        for (int e = 0; e < 3; e++) {
            if (dl[e] <= dr[e]) {
                lo[e]--;
                dl[e] = (lo[e] > 0) ? (xv[e] - smf[lo[e] - 1 + off]) : FLT_MAX;
            } else {
                hi[e]++;
                dr[e] = (hi[e] < NN - 1) ? (smf[hi[e] + 1 + off] - xv[e]) : FLT_MAX;
            }
        }
    }
    #pragma unroll
    for (int e = 0; e < 3; e++) {
        if (e == 2 && !v2) break;
        sdn[pl[e]] = smf[lo[e] + off] - xv[e];
        sdx[pl[e]] = smf[hi[e] + off] - xv[e];
    }
    __syncthreads();

    // ---- channel reduction: lane l owns channels l and l+32; warps stride points
    {
        const int w = t >> 5, l = t & 31;
        const int o0 = l, o1 = l + 32;
        const float w00 = conv_w[o0*2], w10 = conv_w[o0*2+1];
        const float w01 = conv_w[o1*2], w11 = conv_w[o1*2+1];
        const float sc0 = gamma[o0] * rsqrtf(var[o0] + BN_EPS);
        const float sc1 = gamma[o1] * rsqrtf(var[o1] + BN_EPS);
        const float sh0 = beta[o0] - mean[o0] * sc0;
        const float sh1 = beta[o1] - mean[o1] * sc1;
        const bool  p0  = (sc0 >= 0.f), p1 = (sc1 >= 0.f);

        float mx0 = 0.f, s0 = 0.f, mx1 = 0.f, s1 = 0.f;
        for (int p = w; p < 1024; p += 12) {
            float xq = smf[1024 + p];          // middle chunk natural values
            float dn = sdn[p], dx = sdx[p];
            float e0 = p0 ? fmaxf(w00 * dx, w00 * dn) : fminf(w00 * dx, w00 * dn);
            float h0 = fmaxf(fmaf(sc0, fmaf(w10, xq, e0), sh0), 0.f);
            mx0 = fmaxf(mx0, h0); s0 += h0;
            float e1 = p1 ? fmaxf(w01 * dx, w01 * dn) : fminf(w01 * dx, w01 * dn);
            float h1 = fmaxf(fmaf(sc1, fmaf(w11, xq, e1), sh1), 0.f);
            mx1 = fmaxf(mx1, h1); s1 += h1;
        }
        pmx[w][o0] = mx0; pmx[w][o1] = mx1;
        psm[w][o0] = s0;  psm[w][o1] = s1;
    }
    __syncthreads();
    if (t < COUT) {
        float m = 0.f, s = 0.f;
        #pragma unroll
        for (int w = 0; w < 12; w++) { m = fmaxf(m, pmx[w][t]); s += psm[w][t]; }
        unsigned uu = (m > 0.f) ? __float_as_uint(m) : 0u;  // guard -0.0
        atomicMax(&g_rmax[b * COUT + t], uu);
        atomicAdd(&g_rsum[b * COUT + t], s);
    }
}

// ---------------------------------------------------------------------------
// K5: FC from the accumulators. One block, 128 threads (80 active).
// ---------------------------------------------------------------------------
__global__ void __launch_bounds__(128) k_fc(const float* __restrict__ lin_w,
                                            float* __restrict__ out) {
    const int t = threadIdx.x;
    if (t >= NB * NCLASS) return;
    const int b = t / NCLASS, c = t % NCLASS;
    const float* __restrict__ w = lin_w + c * (2 * COUT);
    float acc = 0.f;
    #pragma unroll 8
    for (int o = 0; o < COUT; o++) {
        float x1 = __uint_as_float(g_rmax[b * COUT + o]);
        float x2 = g_rsum[b * COUT + o] * (1.0f / NN);
        acc = fmaf(w[o], x1, acc);
        acc = fmaf(w[COUT + o], x2, acc);
    }
    out[b * NCLASS + c] = acc;
}

// ---------------------------------------------------------------------------
extern "C" void kernel_launch(void* const* d_in, const int* in_sizes, int n_in,
                              void* d_out, int out_size) {
    const float* x      = (const float*)d_in[0];
    const float* conv_w = (const float*)d_in[1];
    const float* gamma  = (const float*)d_in[2];
    const float* beta   = (const float*)d_in[3];
    const float* mean   = (const float*)d_in[4];
    const float* var    = (const float*)d_in[5];
    const float* lin_w  = (const float*)d_in[6];
    float* out = (float*)d_out;

    k_sort1024<<<dim3(8, NB), 128>>>(x);        // x   -> g_A (k<=1024) + zero acc
    k_merge<1><<<dim3(8, NB), 128>>>();         // g_A -> g_B (k=2048)
    k_merge<2><<<dim3(8, NB), 128>>>();         // g_B -> g_A (k=4096)
    k_merge3win_red<<<dim3(8, NB), 384>>>(conv_w, gamma, beta, mean, var);
    k_fc<<<1, 128>>>(lin_w, out);
}

// round 13
// speedup vs baseline: 1.6633x; 1.6633x over previous
#include <cuda_runtime.h>
#include <float.h>

#define NB     2
#define NN     8192
#define KNN    20
#define COUT   64
#define NCLASS 40
#define BN_EPS 1e-5f
#define EPT    8

// Scratch (no allocations allowed)
__device__ alignas(16) float  g_A[NB * NN];
__device__ alignas(16) float  g_B[NB * NN];
__device__ alignas(16) float4 g_pack[NB * NN];   // {x, dmin, dmax, 0}

// ---------------------------------------------------------------------------
// Compare-exchange helpers — ALL register indices compile-time constant.
// Global bitonic rule: at stage k, element i merges ascending iff (i&k)==0.
// ---------------------------------------------------------------------------
__device__ __forceinline__ void ce(float& a, float& b, bool up) {
    float mn = fminf(a, b), mx = fmaxf(a, b);
    a = up ? mn : mx;
    b = up ? mx : mn;
}

__device__ __forceinline__ void reg_merge(float v[EPT], bool d) {
    ce(v[0], v[4], d); ce(v[1], v[5], d); ce(v[2], v[6], d); ce(v[3], v[7], d);
    ce(v[0], v[2], d); ce(v[1], v[3], d); ce(v[4], v[6], d); ce(v[5], v[7], d);
    ce(v[0], v[1], d); ce(v[2], v[3], d); ce(v[4], v[5], d); ce(v[6], v[7], d);
}

__device__ __forceinline__ void sort8(float v[EPT], bool d8) {
    ce(v[0], v[1], true);  ce(v[2], v[3], false);
    ce(v[4], v[5], true);  ce(v[6], v[7], false);
    ce(v[0], v[2], true);  ce(v[1], v[3], true);
    ce(v[4], v[6], false); ce(v[5], v[7], false);
    ce(v[0], v[1], true);  ce(v[2], v[3], true);
    ce(v[4], v[5], false); ce(v[6], v[7], false);
    reg_merge(v, d8);
}

__device__ __forceinline__ void warp_merge(float v[EPT], bool d, int xm_start, int t) {
    for (int xm = xm_start; xm >= 1; xm >>= 1) {
        bool lowup = (((t & xm) == 0) == d);
        #pragma unroll
        for (int m = 0; m < EPT; m++) {
            float pv = __shfl_xor_sync(0xffffffffu, v[m], xm);
            v[m] = lowup ? fminf(v[m], pv) : fmaxf(v[m], pv);
        }
    }
    reg_merge(v, d);
}

// smem substages j = jstart..256 (128-thread block), then intra-warp tail.
__device__ __forceinline__ void block_merge128(float v[EPT], float4* sA, int t,
                                               bool d, int jstart) {
    float4* sB = sA + 128;
    for (int j = jstart; j >= 256; j >>= 1) {
        sA[t] = make_float4(v[0], v[1], v[2], v[3]);
        sB[t] = make_float4(v[4], v[5], v[6], v[7]);
        __syncthreads();
        const int  pt    = t ^ (j >> 3);
        const bool lowup = (((t & (j >> 3)) == 0) == d);
        float4 pa = sA[pt], pb = sB[pt];
        v[0] = lowup ? fminf(v[0], pa.x) : fmaxf(v[0], pa.x);
        v[1] = lowup ? fminf(v[1], pa.y) : fmaxf(v[1], pa.y);
        v[2] = lowup ? fminf(v[2], pa.z) : fmaxf(v[2], pa.z);
        v[3] = lowup ? fminf(v[3], pa.w) : fmaxf(v[3], pa.w);
        v[4] = lowup ? fminf(v[4], pb.x) : fmaxf(v[4], pb.x);
        v[5] = lowup ? fminf(v[5], pb.y) : fmaxf(v[5], pb.y);
        v[6] = lowup ? fminf(v[6], pb.z) : fmaxf(v[6], pb.z);
        v[7] = lowup ? fminf(v[7], pb.w) : fmaxf(v[7], pb.w);
        __syncthreads();
    }
    warp_merge(v, d, 16, t);
}

__device__ __forceinline__ float4 f4ce(float4 a, float4 b, bool mn) {
    float4 r;
    r.x = mn ? fminf(a.x, b.x) : fmaxf(a.x, b.x);
    r.y = mn ? fminf(a.y, b.y) : fmaxf(a.y, b.y);
    r.z = mn ? fminf(a.z, b.z) : fmaxf(a.z, b.z);
    r.w = mn ? fminf(a.w, b.w) : fmaxf(a.w, b.w);
    return r;
}

// ---------------------------------------------------------------------------
// K1: sort each 1024-chunk (k = 2..1024). grid (8, NB) x 128 threads. x -> g_A.
// Also zeroes d_out (poisoned by harness) for the atomic FC accumulation.
// ---------------------------------------------------------------------------
__global__ void __launch_bounds__(128, 1) k_sort1024(const float* __restrict__ x,
                                                     float* __restrict__ out) {
    __shared__ float4 s[256];
    const int t = threadIdx.x;
    const int b = blockIdx.y, cx = blockIdx.x;
    if (b == 0 && cx == 0 && t < NB * NCLASS) out[t] = 0.f;

    const float4* src = (const float4*)(x + b * NN + cx * 1024);
    float v[EPT];
    { float4 a = src[t * 2], c = src[t * 2 + 1];
      v[0]=a.x; v[1]=a.y; v[2]=a.z; v[3]=a.w;
      v[4]=c.x; v[5]=c.y; v[6]=c.z; v[7]=c.w; }

    sort8(v, (t & 1) == 0);                            // k = 2,4,8
    for (int k = 16; k <= 256; k <<= 1)                // k = 16..256
        warp_merge(v, (t & (k >> 3)) == 0, k >> 4, t);
    block_merge128(v, s, t, (t & 64) == 0, 256);       // k = 512
    block_merge128(v, s, t, (cx & 1) == 0, 512);       // k = 1024

    float4* dst = (float4*)(g_A + b * NN + cx * 1024);
    dst[t * 2]     = make_float4(v[0], v[1], v[2], v[3]);
    dst[t * 2 + 1] = make_float4(v[4], v[5], v[6], v[7]);
}

// ---------------------------------------------------------------------------
// Merge stage for k = 1024<<L (cross substages as load-time butterflies).
// grid (8, NB) x 128 threads. L=1: g_A->g_B. L=2: g_B->g_A. L=3: g_A->g_B.
// (Proven R7; src/dst selected in device code.)
// ---------------------------------------------------------------------------
template<int L>
__global__ void __launch_bounds__(128, 1) k_merge() {
    __shared__ float4 s[256];
    const int t = threadIdx.x;
    const int b = blockIdx.y, cx = blockIdx.x;
    const float* __restrict__ srcp = (L == 2) ? g_B : g_A;
    float*       __restrict__ dstp = (L == 2) ? g_A : g_B;
    const float4* src = (const float4*)(srcp + b * NN);

    bool asc, km1, km2 = false, km3 = false;
    if (L == 1) {
        asc = ((cx >> 1) & 1) == 0;
        km1 = asc == ((cx & 1) == 0);
    } else if (L == 2) {
        asc = ((cx >> 2) & 1) == 0;
        km1 = asc == (((cx >> 1) & 1) == 0);
        km2 = asc == ((cx & 1) == 0);
    } else {
        asc = true;
        km1 = (cx & 4) == 0;
        km2 = (cx & 2) == 0;
        km3 = (cx & 1) == 0;
    }

    float v[EPT];
    #pragma unroll
    for (int g = 0; g < 2; g++) {
        const int o = t * 2 + g;
        float4 r;
        if (L == 1) {
            r = f4ce(src[cx * 256 + o], src[(cx ^ 1) * 256 + o], km1);
        } else if (L == 2) {
            float4 a0 = src[cx * 256 + o],       a1 = src[(cx ^ 1) * 256 + o];
            float4 a2 = src[(cx ^ 2) * 256 + o], a3 = src[(cx ^ 3) * 256 + o];
            r = f4ce(f4ce(a0, a2, km1), f4ce(a1, a3, km1), km2);
        } else {
            float4 a0 = src[cx * 256 + o],       a1 = src[(cx ^ 1) * 256 + o];
            float4 a2 = src[(cx ^ 2) * 256 + o], a3 = src[(cx ^ 3) * 256 + o];
            float4 a4 = src[(cx ^ 4) * 256 + o], a5 = src[(cx ^ 5) * 256 + o];
            float4 a6 = src[(cx ^ 6) * 256 + o], a7 = src[(cx ^ 7) * 256 + o];
            float4 u0 = f4ce(a0, a4, km1), u2 = f4ce(a2, a6, km1);
            float4 u1 = f4ce(a1, a5, km1), u3 = f4ce(a3, a7, km1);
            r = f4ce(f4ce(u0, u2, km2), f4ce(u1, u3, km2), km3);
        }
        v[g * 4 + 0] = r.x; v[g * 4 + 1] = r.y;
        v[g * 4 + 2] = r.z; v[g * 4 + 3] = r.w;
    }

    block_merge128(v, s, t, asc, 512);

    float4* dst = (float4*)(dstp + b * NN + cx * 1024);
    dst[t * 2]     = make_float4(v[0], v[1], v[2], v[3]);
    dst[t * 2 + 1] = make_float4(v[4], v[5], v[6], v[7]);
}

// ---------------------------------------------------------------------------
// Window: K-nearest window per point (smem halo +-19). grid (32, NB) x 256.
// Reads g_B (final sorted). (Proven R7.)
// ---------------------------------------------------------------------------
__global__ void __launch_bounds__(256) k_window() {
    __shared__ float sw[256 + 2 * (KNN - 1) + 2];
    const int b = blockIdx.y;
    const int p0 = blockIdx.x * 256;
    const float* __restrict__ src = g_B + b * NN;

    for (int i = threadIdx.x; i < 256 + 2 * (KNN - 1); i += 256) {
        int g = p0 - (KNN - 1) + i;
        sw[i] = (g >= 0 && g < NN) ? src[g] : 0.f;   // halo garbage never read
    }
    __syncthreads();

    const int p   = p0 + threadIdx.x;
    const int off = (KNN - 1) - p0;
    const float xv = sw[p + off];
    int lo = p, hi = p;
    float dl = (lo > 0)      ? (xv - sw[lo - 1 + off]) : FLT_MAX;
    float dr = (hi < NN - 1) ? (sw[hi + 1 + off] - xv) : FLT_MAX;
    #pragma unroll
    for (int it = 1; it < KNN; it++) {
        if (dl <= dr) {
            lo--;
            dl = (lo > 0) ? (xv - sw[lo - 1 + off]) : FLT_MAX;
        } else {
            hi++;
            dr = (hi < NN - 1) ? (sw[hi + 1 + off] - xv) : FLT_MAX;
        }
    }
    g_pack[b * NN + p] = make_float4(xv, sw[lo + off] - xv, sw[hi + off] - xv, 0.f);
}

// ---------------------------------------------------------------------------
// Reduce v2 (max & mean per (batch,channel)) + fused FC via atomicAdd.
// 512 threads, 16 points/thread FULLY UNROLLED (MLP=16 -> ~2 exposed L2
// round-trips instead of ~8), warp shfl reduce + 16-partial smem fold.
// ---------------------------------------------------------------------------
__global__ void __launch_bounds__(512) reduce_fc(const float* __restrict__ conv_w,
                                                 const float* __restrict__ gamma,
                                                 const float* __restrict__ beta,
                                                 const float* __restrict__ mean,
                                                 const float* __restrict__ var,
                                                 const float* __restrict__ lin_w,
                                                 float* __restrict__ out) {
    __shared__ float smx[16], ssm[16], bx1, bx2;
    const int b = blockIdx.x >> 6;
    const int o = blockIdx.x & 63;
    const int t = threadIdx.x;

    const float w0 = conv_w[o * 2 + 0];
    const float w1 = conv_w[o * 2 + 1];
    const float sc = gamma[o] * rsqrtf(var[o] + BN_EPS);
    const float sh = beta[o] - mean[o] * sc;
    const bool pos = (sc >= 0.f);

    const float4* __restrict__ gp = g_pack + b * NN;
    float4 q[16];
    #pragma unroll
    for (int i = 0; i < 16; i++) q[i] = gp[t + i * 512];   // 16 loads in flight

    float mx = 0.f, sum = 0.f;
    #pragma unroll
    for (int i = 0; i < 16; i++) {
        float e = pos ? fmaxf(w0 * q[i].y, w0 * q[i].z)
                      : fminf(w0 * q[i].y, w0 * q[i].z);
        float h = fmaxf(fmaf(sc, fmaf(w1, q[i].x, e), sh), 0.f);
        mx = fmaxf(mx, h);
        sum += h;
    }
    #pragma unroll
    for (int off = 16; off > 0; off >>= 1) {
        mx  = fmaxf(mx, __shfl_xor_sync(0xffffffffu, mx, off));
        sum += __shfl_xor_sync(0xffffffffu, sum, off);
    }
    const int warp = t >> 5, lane = t & 31;
    if (lane == 0) { smx[warp] = mx; ssm[warp] = sum; }
    __syncthreads();
    if (t == 0) {
        float fmx = smx[0], fsm = ssm[0];
        #pragma unroll
        for (int w = 1; w < 16; w++) { fmx = fmaxf(fmx, smx[w]); fsm += ssm[w]; }
        bx1 = fmx;
        bx2 = fsm * (1.0f / NN);
    }
    __syncthreads();
    if (t < NCLASS) {
        const int c = t;
        float contr = lin_w[c * (2 * COUT) + o]        * bx1
                    + lin_w[c * (2 * COUT) + COUT + o] * bx2;
        atomicAdd(&out[b * NCLASS + c], contr);
    }
}

// ---------------------------------------------------------------------------
extern "C" void kernel_launch(void* const* d_in, const int* in_sizes, int n_in,
                              void* d_out, int out_size) {
    const float* x      = (const float*)d_in[0];
    const float* conv_w = (const float*)d_in[1];
    const float* gamma  = (const float*)d_in[2];
    const float* beta   = (const float*)d_in[3];
    const float* mean   = (const float*)d_in[4];
    const float* var    = (const float*)d_in[5];
    const float* lin_w  = (const float*)d_in[6];
    float* out = (float*)d_out;

    k_sort1024<<<dim3(8, NB), 128>>>(x, out);   // x   -> g_A (k <= 1024)
    k_merge<1><<<dim3(8, NB), 128>>>();         // g_A -> g_B (k = 2048)
    k_merge<2><<<dim3(8, NB), 128>>>();         // g_B -> g_A (k = 4096)
    k_merge<3><<<dim3(8, NB), 128>>>();         // g_A -> g_B (k = 8192)
    k_window<<<dim3(32, NB), 256>>>();          // g_B -> g_pack
    reduce_fc<<<NB * COUT, 512>>>(conv_w, gamma, beta, mean, var, lin_w, out);
}